// round 13
// baseline (speedup 1.0000x reference)
#include <cuda_runtime.h>
#include <math.h>
#include <stdint.h>

#define SQ   1024
#define HIDN 4096
#define NH   32
#define HD   128
#define KBN  2048
#define KBSTRIDE 8192   // NUM_SLOTS * HID
#define NTOP 100
#define ATT_SCALE 0.08838834764831845f  // 1/sqrt(128)

#define BMQ 64
#define BNK 64

// ---- attention smem layout (floats), strides chosen for conflict-free frags
#define QSTR 132
#define KSTR 132
#define VSTR 136
#define SSTR 68
#define QS_OFF   0
#define KV_OFF   (64*QSTR)
#define SS_OFF   (KV_OFF + 64*VSTR)
#define MROW_OFF (SS_OFF + 64*SSTR)
#define LROW_OFF (MROW_OFF + 64)
#define CROW_OFF (LROW_OFF + 64)
#define MNEW_OFF (CROW_OFF + 64)
#define PMAX_OFF (MNEW_OFF + 64)
#define PSUM_OFF (PMAX_OFF + 256)
#define ATTN_SMEM ((PSUM_OFF + 256) * 4)      // 89088 bytes

// ---------------- device scratch (static, allocation-free) ----------------
__device__ float g_xq  [SQ*HIDN];
__device__ float g_xq2 [SQ*HIDN];
__device__ float g_xk  [SQ*HIDN];
__device__ float g_xv  [SQ*HIDN];
__device__ float g_attn[SQ*HIDN];   // tf32-rounded by attn epilogue
__device__ float g_hst [SQ*HIDN];   // tf32-rounded copy of hidden_states
__device__ float g_hsum [HIDN];
__device__ float g_q2sum[HIDN];
__device__ float g_kbscore[KBN];
__device__ int   g_topidx[NTOP];

// ======================= tf32 mma.sync GEMM ================================
// CTA tile 128x256, warp tile 64x64 (8 warps, 2m x 4n). TBK=32, 3-stage
// cp.async ring, branch-free mainloop. A pre-rounded to tf32 (no CVT on A).
// Fragment loads LDS.32 with conflict-free banks (4g+tig, stride 36).
#define TBM 128
#define TBN 256
#define TBK 32
#define TSTR 36                            // 32 data + 4 pad
#define NSTG 3
#define STGF ((TBM + TBN) * TSTR)          // 13824 floats / stage
#define GEMM_SMEM (NSTG * STGF * 4)        // 165888 bytes

struct GemmPtrs {
    const float* B[4];
    float*       C[4];
};

__device__ __forceinline__ uint32_t smem_u32(const void* p) {
    uint32_t a;
    asm("{ .reg .u64 t; cvta.to.shared.u64 t, %1; cvt.u32.u64 %0, t; }"
        : "=r"(a) : "l"(p));
    return a;
}
__device__ __forceinline__ void cp16(uint32_t s, const void* g) {
    asm volatile("cp.async.cg.shared.global [%0], [%1], 16;" :: "r"(s), "l"(g) : "memory");
}
__device__ __forceinline__ uint32_t f2tf32(float f) {
    uint32_t u;
    asm("cvt.rna.tf32.f32 %0, %1;" : "=r"(u) : "f"(f));
    return u;
}
__device__ __forceinline__ void mma_tf32(float* c, const uint32_t* a, const uint32_t* b) {
    asm volatile(
        "mma.sync.aligned.m16n8k8.row.col.f32.tf32.tf32.f32 "
        "{%0,%1,%2,%3}, {%4,%5,%6,%7}, {%8,%9}, {%0,%1,%2,%3};"
        : "+f"(c[0]), "+f"(c[1]), "+f"(c[2]), "+f"(c[3])
        : "r"(a[0]), "r"(a[1]), "r"(a[2]), "r"(a[3]), "r"(b[0]), "r"(b[1]));
}

__device__ __forceinline__ void g_load_stage(
    uint32_t soff, const float* __restrict__ Ab, const float* __restrict__ Bb,
    int k0, int tid, int K)
{
    uint32_t dA = soff;
    uint32_t dB = soff + TBM * TSTR * 4;
    #pragma unroll
    for (int j = 0; j < 4; j++) {                 // A: 128 rows x 8 granules
        int gi  = tid + 256 * j;
        int row = gi >> 3, c = (gi & 7) * 4;
        cp16(dA + (row * TSTR + c) * 4, Ab + (size_t)row * K + k0 + c);
    }
    #pragma unroll
    for (int j = 0; j < 8; j++) {                 // B: 256 rows x 8 granules
        int gi  = tid + 256 * j;
        int row = gi >> 3, c = (gi & 7) * 4;
        cp16(dB + (row * TSTR + c) * 4, Bb + (size_t)row * K + k0 + c);
    }
    asm volatile("cp.async.commit_group;" ::: "memory");
}

// A pre-rounded: no CVT on A fragments. B cvt'd in-loop. LDS.32 throughout.
__device__ __forceinline__ void g_compute_stage(
    const float* a_s, const float* b_s, float acc[4][8][4],
    int wm, int wn, int g, int tig)
{
    #pragma unroll
    for (int ks = 0; ks < 4; ks++) {
        int kb = ks * 8;
        uint32_t af[4][4];
        #pragma unroll
        for (int mt = 0; mt < 4; mt++) {
            int r = wm + mt * 16 + g;
            af[mt][0] = __float_as_uint(a_s[ r      * TSTR + kb + tig]);
            af[mt][1] = __float_as_uint(a_s[(r + 8) * TSTR + kb + tig]);
            af[mt][2] = __float_as_uint(a_s[ r      * TSTR + kb + tig + 4]);
            af[mt][3] = __float_as_uint(a_s[(r + 8) * TSTR + kb + tig + 4]);
        }
        uint32_t bf[8][2];
        #pragma unroll
        for (int nt = 0; nt < 8; nt++) {
            int n = wn + nt * 8 + g;
            bf[nt][0] = f2tf32(b_s[n * TSTR + kb + tig]);
            bf[nt][1] = f2tf32(b_s[n * TSTR + kb + tig + 4]);
        }
        #pragma unroll
        for (int mt = 0; mt < 4; mt++)
            #pragma unroll
            for (int nt = 0; nt < 8; nt++)
                mma_tf32(acc[mt][nt], af[mt], bf[nt]);
    }
}

__global__ __launch_bounds__(256, 1) void gemm_tf32(
    const float* __restrict__ A, GemmPtrs p, int M, int N, int K)
{
    extern __shared__ float gsm[];
    const float* B = p.B[blockIdx.z];
    float*       C = p.C[blockIdx.z];

    int tid  = threadIdx.x;
    int wid  = tid >> 5;
    int lane = tid & 31;
    int bm = blockIdx.y * TBM, bn = blockIdx.x * TBN;

    int wm  = (wid & 1) * 64;
    int wn  = (wid >> 1) * 64;
    int g   = lane >> 2;
    int tig = lane & 3;

    uint32_t sbase = smem_u32(gsm);
    const float* Ab = A + (size_t)bm * K;
    const float* Bb = B + (size_t)bn * K;

    float acc[4][8][4];
    #pragma unroll
    for (int i = 0; i < 4; i++)
        #pragma unroll
        for (int j = 0; j < 8; j++)
            #pragma unroll
            for (int r = 0; r < 4; r++) acc[i][j][r] = 0.f;

    const int NIT = K / TBK;   // 128

    g_load_stage(sbase,            Ab, Bb, 0,   tid, K);
    g_load_stage(sbase + STGF * 4, Ab, Bb, TBK, tid, K);

    int cur = 0;
    for (int it = 0; it < NIT - 2; it++) {
        asm volatile("cp.async.wait_group 1;" ::: "memory");
        __syncthreads();
        int s2 = cur + 2; if (s2 >= NSTG) s2 -= NSTG;
        g_load_stage(sbase + s2 * STGF * 4, Ab, Bb, (it + 2) * TBK, tid, K);
        const float* a_s = gsm + cur * STGF;
        g_compute_stage(a_s, a_s + TBM * TSTR, acc, wm, wn, g, tig);
        if (++cur == NSTG) cur = 0;
    }
    asm volatile("cp.async.wait_group 1;" ::: "memory");
    __syncthreads();
    {
        const float* a_s = gsm + cur * STGF;
        g_compute_stage(a_s, a_s + TBM * TSTR, acc, wm, wn, g, tig);
        if (++cur == NSTG) cur = 0;
    }
    asm volatile("cp.async.wait_group 0;" ::: "memory");
    __syncthreads();
    {
        const float* a_s = gsm + cur * STGF;
        g_compute_stage(a_s, a_s + TBM * TSTR, acc, wm, wn, g, tig);
    }

    #pragma unroll
    for (int mt = 0; mt < 4; mt++) {
        #pragma unroll
        for (int nt = 0; nt < 8; nt++) {
            int row = bm + wm + mt * 16 + g;
            int col = bn + wn + nt * 8 + 2 * tig;
            float* c0 = C + (size_t)row * N + col;
            float* c1 = C + (size_t)(row + 8) * N + col;
            ((float2*)c0)[0] = make_float2(acc[mt][nt][0], acc[mt][nt][1]);
            ((float2*)c1)[0] = make_float2(acc[mt][nt][2], acc[mt][nt][3]);
        }
    }
}

// ---------------- tf32 pre-round of hidden_states (+ zero g_hsum) ---------
__global__ void rnd_kernel(const float* __restrict__ hs)
{
    int i = blockIdx.x * 256 + threadIdx.x;
    float4 v = ((const float4*)hs)[i];
    v.x = __uint_as_float(f2tf32(v.x));
    v.y = __uint_as_float(f2tf32(v.y));
    v.z = __uint_as_float(f2tf32(v.z));
    v.w = __uint_as_float(f2tf32(v.w));
    ((float4*)g_hst)[i] = v;
    if (i < HIDN) g_hsum[i] = 0.f;
}

// ---------------- RoPE in place on g_xq and g_xk --------------------------
__global__ void rope_kernel(const int* __restrict__ pos_ids)
{
    const int total = SQ * HIDN / 2;
    int i = blockIdx.x * blockDim.x + threadIdx.x;
    float* X = g_xq;
    if (i >= total) { X = g_xk; i -= total; }
    if (i >= total) return;
    int s = i / (HIDN/2);
    int r = i - s * (HIDN/2);
    int h = r >> 6, d = r & 63;
    int c = s*HIDN + h*HD + d;
    float pos = (float)pos_ids[s];
    float inv = expf((float)d * (-9.210340371976184f / 64.0f));
    float f = pos * inv;
    float cs, sn;
    sincosf(f, &sn, &cs);
    float x1 = X[c], x2 = X[c + 64];
    X[c]      = x1*cs - x2*sn;
    X[c + 64] = x2*cs + x1*sn;
}

// ---------------- fp32 top-k scoring path ---------------------------------
__global__ void hsum_kernel(const float* __restrict__ hs)
{
    int c  = blockIdx.x * 256 + threadIdx.x;
    int r0 = blockIdx.y * (SQ / 8);
    float s = 0.f;
    for (int r = r0; r < r0 + SQ / 8; r++) s += hs[(size_t)r*HIDN + c];
    atomicAdd(&g_hsum[c], s);
}

__global__ void q2sum_kernel(const float* __restrict__ Wq2)
{
    int n    = blockIdx.x * 8 + (threadIdx.x >> 5);
    int lane = threadIdx.x & 31;
    const float* row = Wq2 + (size_t)n * HIDN;
    float s = 0.f;
    for (int i = lane; i < HIDN; i += 32) s += row[i] * g_hsum[i];
    #pragma unroll
    for (int o = 16; o; o >>= 1) s += __shfl_xor_sync(0xffffffffu, s, o);
    if (lane == 0) g_q2sum[n] = s;
}

__global__ void kbscore_kernel(const float* __restrict__ kb_keys)
{
    int kb   = blockIdx.x * 8 + (threadIdx.x >> 5);
    int lane = threadIdx.x & 31;
    const float* row = kb_keys + (size_t)kb * KBSTRIDE;
    float s = 0.f;
    for (int i = lane; i < HIDN; i += 32) s += row[i] * g_q2sum[i];
    #pragma unroll
    for (int o = 16; o; o >>= 1) s += __shfl_xor_sync(0xffffffffu, s, o);
    if (lane == 0) g_kbscore[kb] = s;
}

__global__ void topk_kernel()
{
    __shared__ float sv[KBN];
    __shared__ float rv[256];
    __shared__ int   ri[256];
    int t = threadIdx.x;
    for (int i = t; i < KBN; i += 256) sv[i] = g_kbscore[i];
    __syncthreads();
    for (int it = 0; it < NTOP; it++) {
        float best = -INFINITY; int bi = 0;
        for (int i = t; i < KBN; i += 256) {
            float v = sv[i];
            if (v > best) { best = v; bi = i; }
        }
        rv[t] = best; ri[t] = bi;
        __syncthreads();
        for (int o = 128; o; o >>= 1) {
            if (t < o && rv[t+o] > rv[t]) { rv[t] = rv[t+o]; ri[t] = ri[t+o]; }
            __syncthreads();
        }
        if (t == 0) { g_topidx[it] = ri[0]; sv[ri[0]] = -INFINITY; }
        __syncthreads();
    }
}

// ---------------- mma.sync flash attention over [KB-topk ; causal self] ---
__global__ __launch_bounds__(256, 2) void attn_kernel(
    const float* __restrict__ kb_keys, const float* __restrict__ kb_values,
    const float* __restrict__ score_shift)
{
    extern __shared__ float sm[];
    float* Qs   = sm + QS_OFF;
    float* KVs  = sm + KV_OFF;
    float* Ss   = sm + SS_OFF;
    float* mrow = sm + MROW_OFF;
    float* lrow = sm + LROW_OFF;
    float* crow = sm + CROW_OFF;
    float* mnew = sm + MNEW_OFF;
    float* pmax = sm + PMAX_OFF;
    float* psum = sm + PSUM_OFF;

    int h  = blockIdx.y;
    int q0 = blockIdx.x * BMQ;
    int tid  = threadIdx.x;
    int wid  = tid >> 5;
    int lane = tid & 31;
    int g    = lane >> 2;
    int tig  = lane & 3;
    int wm   = (wid & 1) * 32;
    int wgrp = wid >> 1;
    int wn   = wgrp * 16;
    int wd   = wgrp * 32;

    float oacc[2][4][4];
    #pragma unroll
    for (int mt = 0; mt < 2; mt++)
        #pragma unroll
        for (int nt = 0; nt < 4; nt++)
            #pragma unroll
            for (int r = 0; r < 4; r++) oacc[mt][nt][r] = 0.f;

    if (tid < BMQ) { mrow[tid] = -INFINITY; lrow[tid] = 0.f; }
    float shift = score_shift[h];

    const int nkb    = (NTOP + BNK - 1) / BNK;   // 2
    const int ntiles = nkb + blockIdx.x + 1;

    for (int t = 0; t < ntiles; t++) {
        bool kbphase = (t < nkb);
        int  kb0   = (t - nkb) * BNK;
        int  jbase = t * BNK;

        if (t == 0 || t == nkb) {
            const float* src = kbphase ? g_xq2 : g_xq;
            for (int i = tid; i < BMQ*32; i += 256) {
                int row = i >> 5, c4 = i & 31;
                ((float4*)Qs)[row*33 + c4] =
                    ((const float4*)(src + (size_t)(q0+row)*HIDN + h*HD))[c4];
            }
        }
        for (int i = tid; i < BNK*32; i += 256) {
            int row = i >> 5, c4 = i & 31;
            float4 v;
            if (kbphase) {
                int j = jbase + row;
                if (j < NTOP) {
                    int kb = g_topidx[j];
                    v = ((const float4*)(kb_keys + (size_t)kb*KBSTRIDE + h*HD))[c4];
                } else v = make_float4(0.f,0.f,0.f,0.f);
            } else {
                v = ((const float4*)(g_xk + (size_t)(kb0+row)*HIDN + h*HD))[c4];
            }
            ((float4*)KVs)[row*33 + c4] = v;
        }
        __syncthreads();

        float sacc[2][2][4];
        #pragma unroll
        for (int mt = 0; mt < 2; mt++)
            #pragma unroll
            for (int nt = 0; nt < 2; nt++)
                #pragma unroll
                for (int r = 0; r < 4; r++) sacc[mt][nt][r] = 0.f;

        #pragma unroll 4
        for (int ks = 0; ks < 16; ks++) {
            int kb = ks * 8;
            uint32_t af[2][4];
            #pragma unroll
            for (int mt = 0; mt < 2; mt++) {
                int r = wm + mt * 16 + g;
                af[mt][0] = f2tf32(Qs[ r      * QSTR + kb + tig]);
                af[mt][1] = f2tf32(Qs[(r + 8) * QSTR + kb + tig]);
                af[mt][2] = f2tf32(Qs[ r      * QSTR + kb + tig + 4]);
                af[mt][3] = f2tf32(Qs[(r + 8) * QSTR + kb + tig + 4]);
            }
            uint32_t bf[2][2];
            #pragma unroll
            for (int nt = 0; nt < 2; nt++) {
                int n = wn + nt * 8 + g;
                bf[nt][0] = f2tf32(KVs[n * KSTR + kb + tig]);
                bf[nt][1] = f2tf32(KVs[n * KSTR + kb + tig + 4]);
            }
            #pragma unroll
            for (int mt = 0; mt < 2; mt++)
                #pragma unroll
                for (int nt = 0; nt < 2; nt++)
                    mma_tf32(sacc[mt][nt], af[mt], bf[nt]);
        }

        float lm0[2], lm1[2];
        #pragma unroll
        for (int mt = 0; mt < 2; mt++) { lm0[mt] = -INFINITY; lm1[mt] = -INFINITY; }
        #pragma unroll
        for (int mt = 0; mt < 2; mt++) {
            int r = wm + mt * 16 + g;
            #pragma unroll
            for (int nt = 0; nt < 2; nt++) {
                int colb = wn + nt * 8 + 2 * tig;
                #pragma unroll
                for (int c = 0; c < 2; c++) {
                    int kk = colb + c;
                    float s0 = sacc[mt][nt][c] * ATT_SCALE;
                    float s1 = sacc[mt][nt][2+c] * ATT_SCALE;
                    bool v0, v1;
                    if (kbphase) {
                        s0 += shift; s1 += shift;
                        v0 = (jbase + kk < NTOP); v1 = v0;
                    } else {
                        v0 = (kb0 + kk <= q0 + r);
                        v1 = (kb0 + kk <= q0 + r + 8);
                    }
                    s0 = v0 ? s0 : -INFINITY;
                    s1 = v1 ? s1 : -INFINITY;
                    sacc[mt][nt][c]   = s0;
                    sacc[mt][nt][2+c] = s1;
                    lm0[mt] = fmaxf(lm0[mt], s0);
                    lm1[mt] = fmaxf(lm1[mt], s1);
                }
            }
        }
        #pragma unroll
        for (int o = 1; o < 4; o <<= 1)
            #pragma unroll
            for (int mt = 0; mt < 2; mt++) {
                lm0[mt] = fmaxf(lm0[mt], __shfl_xor_sync(0xffffffffu, lm0[mt], o));
                lm1[mt] = fmaxf(lm1[mt], __shfl_xor_sync(0xffffffffu, lm1[mt], o));
            }
        if (tig == 0) {
            #pragma unroll
            for (int mt = 0; mt < 2; mt++) {
                pmax[(wm + mt*16 + g    ) * 4 + wgrp] = lm0[mt];
                pmax[(wm + mt*16 + g + 8) * 4 + wgrp] = lm1[mt];
            }
        }
        __syncthreads();

        if (tid < BMQ) {
            float mo = mrow[tid];
            float mx = fmaxf(fmaxf(pmax[tid*4], pmax[tid*4+1]),
                             fmaxf(pmax[tid*4+2], pmax[tid*4+3]));
            mx = fmaxf(mo, mx);
            mnew[tid] = mx;
            crow[tid] = (mo == -INFINITY) ? 0.f : __expf(mo - mx);
        }
        for (int i = tid; i < BNK*32; i += 256) {
            int row = i >> 5, c4 = i & 31;
            float4 v;
            if (kbphase) {
                int j = jbase + row;
                if (j < NTOP) {
                    int kb = g_topidx[j];
                    v = ((const float4*)(kb_values + (size_t)kb*KBSTRIDE + h*HD))[c4];
                } else v = make_float4(0.f,0.f,0.f,0.f);
            } else {
                v = ((const float4*)(g_xv + (size_t)(kb0+row)*HIDN + h*HD))[c4];
            }
            ((float4*)KVs)[row*34 + c4] = v;
        }
        __syncthreads();

        float ls0[2] = {0.f, 0.f}, ls1[2] = {0.f, 0.f};
        #pragma unroll
        for (int mt = 0; mt < 2; mt++) {
            int r = wm + mt * 16 + g;
            float mx0 = mnew[r], mx1 = mnew[r + 8];
            #pragma unroll
            for (int nt = 0; nt < 2; nt++) {
                int colb = wn + nt * 8 + 2 * tig;
                #pragma unroll
                for (int c = 0; c < 2; c++) {
                    float p0 = __expf(sacc[mt][nt][c]   - mx0);
                    float p1 = __expf(sacc[mt][nt][2+c] - mx1);
                    sacc[mt][nt][c]   = p0;
                    sacc[mt][nt][2+c] = p1;
                    ls0[mt] += p0; ls1[mt] += p1;
                }
                Ss[ r      * SSTR + colb    ] = sacc[mt][nt][0];
                Ss[ r      * SSTR + colb + 1] = sacc[mt][nt][1];
                Ss[(r + 8) * SSTR + colb    ] = sacc[mt][nt][2];
                Ss[(r + 8) * SSTR + colb + 1] = sacc[mt][nt][3];
            }
        }
        #pragma unroll
        for (int o = 1; o < 4; o <<= 1)
            #pragma unroll
            for (int mt = 0; mt < 2; mt++) {
                ls0[mt] += __shfl_xor_sync(0xffffffffu, ls0[mt], o);
                ls1[mt] += __shfl_xor_sync(0xffffffffu, ls1[mt], o);
            }
        if (tig == 0) {
            #pragma unroll
            for (int mt = 0; mt < 2; mt++) {
                psum[(wm + mt*16 + g    ) * 4 + wgrp] = ls0[mt];
                psum[(wm + mt*16 + g + 8) * 4 + wgrp] = ls1[mt];
            }
        }
        __syncthreads();

        if (tid < BMQ) {
            lrow[tid] = lrow[tid] * crow[tid]
                      + psum[tid*4] + psum[tid*4+1] + psum[tid*4+2] + psum[tid*4+3];
            mrow[tid] = mnew[tid];
        }
        #pragma unroll
        for (int mt = 0; mt < 2; mt++) {
            float c0 = crow[wm + mt*16 + g];
            float c1 = crow[wm + mt*16 + g + 8];
            #pragma unroll
            for (int nt = 0; nt < 4; nt++) {
                oacc[mt][nt][0] *= c0; oacc[mt][nt][1] *= c0;
                oacc[mt][nt][2] *= c1; oacc[mt][nt][3] *= c1;
            }
        }
        #pragma unroll 2
        for (int ks = 0; ks < 8; ks++) {
            int kb = ks * 8;
            uint32_t af[2][4];
            #pragma unroll
            for (int mt = 0; mt < 2; mt++) {
                int r = wm + mt * 16 + g;
                af[mt][0] = f2tf32(Ss[ r      * SSTR + kb + tig]);
                af[mt][1] = f2tf32(Ss[(r + 8) * SSTR + kb + tig]);
                af[mt][2] = f2tf32(Ss[ r      * SSTR + kb + tig + 4]);
                af[mt][3] = f2tf32(Ss[(r + 8) * SSTR + kb + tig + 4]);
            }
            uint32_t bf[4][2];
            #pragma unroll
            for (int nt = 0; nt < 4; nt++) {
                int n = wd + nt * 8 + g;
                bf[nt][0] = f2tf32(KVs[(kb + tig    ) * VSTR + n]);
                bf[nt][1] = f2tf32(KVs[(kb + tig + 4) * VSTR + n]);
            }
            #pragma unroll
            for (int mt = 0; mt < 2; mt++)
                #pragma unroll
                for (int nt = 0; nt < 4; nt++)
                    mma_tf32(oacc[mt][nt], af[mt], bf[nt]);
        }
        __syncthreads();
    }

    // output: tf32-rounded so Wo GEMM can use bits directly as A operand
    #pragma unroll
    for (int mt = 0; mt < 2; mt++) {
        int r = wm + mt * 16 + g;
        float il0 = 1.f / lrow[r];
        float il1 = 1.f / lrow[r + 8];
        float* b0 = g_attn + (size_t)(q0 + r    ) * HIDN + h*HD + wd;
        float* b1 = g_attn + (size_t)(q0 + r + 8) * HIDN + h*HD + wd;
        #pragma unroll
        for (int nt = 0; nt < 4; nt++) {
            int co = nt * 8 + 2 * tig;
            ((float2*)(b0 + co))[0] = make_float2(
                __uint_as_float(f2tf32(oacc[mt][nt][0]*il0)),
                __uint_as_float(f2tf32(oacc[mt][nt][1]*il0)));
            ((float2*)(b1 + co))[0] = make_float2(
                __uint_as_float(f2tf32(oacc[mt][nt][2]*il1)),
                __uint_as_float(f2tf32(oacc[mt][nt][3]*il1)));
        }
    }
}

// ---------------- launch ---------------------------------------------------
extern "C" void kernel_launch(void* const* d_in, const int* in_sizes, int n_in,
                              void* d_out, int out_size)
{
    const float* hs   = (const float*)d_in[0];
    const int*   pos  = (const int*)  d_in[2];
    const float* kbk  = (const float*)d_in[3];
    const float* kbv  = (const float*)d_in[4];
    const float* Wq   = (const float*)d_in[5];
    const float* Wq2  = (const float*)d_in[6];
    const float* Wk   = (const float*)d_in[7];
    const float* Wv   = (const float*)d_in[8];
    const float* Wo   = (const float*)d_in[9];
    const float* shft = (const float*)d_in[10];
    float* out = (float*)d_out;

    float *xq, *xq2, *xk, *xv, *attn, *hst;
    cudaGetSymbolAddress((void**)&xq,   g_xq);
    cudaGetSymbolAddress((void**)&xq2,  g_xq2);
    cudaGetSymbolAddress((void**)&xk,   g_xk);
    cudaGetSymbolAddress((void**)&xv,   g_xv);
    cudaGetSymbolAddress((void**)&attn, g_attn);
    cudaGetSymbolAddress((void**)&hst,  g_hst);

    cudaFuncSetAttribute(attn_kernel,
        cudaFuncAttributeMaxDynamicSharedMemorySize, ATTN_SMEM);
    cudaFuncSetAttribute(gemm_tf32,
        cudaFuncAttributeMaxDynamicSharedMemorySize, GEMM_SMEM);

    // tf32 pre-round of A operand for projections (also zeroes g_hsum)
    rnd_kernel<<<(SQ*HIDN/4)/256, 256>>>(hs);

    GemmPtrs proj;
    proj.B[0] = Wq;  proj.C[0] = xq;
    proj.B[1] = Wq2; proj.C[1] = xq2;
    proj.B[2] = Wk;  proj.C[2] = xk;
    proj.B[3] = Wv;  proj.C[3] = xv;
    dim3 gproj(HIDN/TBN, SQ/TBM, 4);   // (16, 8, 4)
    gemm_tf32<<<gproj, 256, GEMM_SMEM>>>(hst, proj, SQ, HIDN, HIDN);

    rope_kernel<<<(SQ*HIDN)/256, 256>>>(pos);

    hsum_kernel<<<dim3(HIDN/256, 8), 256>>>(hs);
    q2sum_kernel<<<HIDN/8, 256>>>(Wq2);
    kbscore_kernel<<<KBN/8, 256>>>(kbk);
    topk_kernel<<<1, 256>>>();

    attn_kernel<<<dim3(SQ/BMQ, NH), 256, ATTN_SMEM>>>(kbk, kbv, shft);

    GemmPtrs po;
    po.B[0] = Wo; po.C[0] = out;
    po.B[1] = Wo; po.C[1] = out;
    po.B[2] = Wo; po.C[2] = out;
    po.B[3] = Wo; po.C[3] = out;
    dim3 go(HIDN/TBN, SQ/TBM, 1);      // (16, 8, 1)
    gemm_tf32<<<go, 256, GEMM_SMEM>>>(attn, po, SQ, HIDN, HIDN);
}

// round 14
// speedup vs baseline: 1.0887x; 1.0887x over previous
#include <cuda_runtime.h>
#include <math.h>
#include <stdint.h>

#define SQ   1024
#define HIDN 4096
#define NH   32
#define HD   128
#define KBN  2048
#define KBSTRIDE 8192   // NUM_SLOTS * HID
#define NTOP 100
#define ATT_SCALE 0.08838834764831845f  // 1/sqrt(128)

#define BMQ 64
#define BNK 64

// ---- attention smem layout (floats), strides chosen for conflict-free frags
#define QSTR 132
#define KSTR 132
#define VSTR 136
#define SSTR 68
#define QS_OFF   0
#define KV_OFF   (64*QSTR)
#define SS_OFF   (KV_OFF + 64*VSTR)
#define MROW_OFF (SS_OFF + 64*SSTR)
#define LROW_OFF (MROW_OFF + 64)
#define CROW_OFF (LROW_OFF + 64)
#define MNEW_OFF (CROW_OFF + 64)
#define PMAX_OFF (MNEW_OFF + 64)
#define PSUM_OFF (PMAX_OFF + 256)
#define ATTN_SMEM ((PSUM_OFF + 256) * 4)      // 89088 bytes

// ---------------- device scratch (static, allocation-free) ----------------
__device__ float g_xq  [SQ*HIDN];
__device__ float g_xq2 [SQ*HIDN];
__device__ float g_xk  [SQ*HIDN];
__device__ float g_xv  [SQ*HIDN];
__device__ float g_attn[SQ*HIDN];   // tf32-rounded by attn epilogue
__device__ float g_hst [SQ*HIDN];   // tf32-rounded copy of hidden_states
__device__ float g_hsum [HIDN];
__device__ float g_q2sum[HIDN];
__device__ float g_kbscore[KBN];
__device__ int   g_topidx[NTOP];

// ======================= tf32 mma.sync GEMM ================================
// CTA tile 128x128, 4 warps (2m x 2n), warp tile 64x64. TBK=32, 3-stage
// cp.async ring, branch-free mainloop, 2 CTAs/SM. A pre-rounded to tf32.
// Fragment loads LDS.32 with conflict-free banks (4g+tig, stride 36).
#define TBM 128
#define TBN 128
#define TBK 32
#define TSTR 36                            // 32 data + 4 pad
#define NSTG 3
#define STGF ((TBM + TBN) * TSTR)          // 9216 floats / stage
#define GEMM_SMEM (NSTG * STGF * 4)        // 110592 bytes

struct GemmPtrs {
    const float* B[4];
    float*       C[4];
};

__device__ __forceinline__ uint32_t smem_u32(const void* p) {
    uint32_t a;
    asm("{ .reg .u64 t; cvta.to.shared.u64 t, %1; cvt.u32.u64 %0, t; }"
        : "=r"(a) : "l"(p));
    return a;
}
__device__ __forceinline__ void cp16(uint32_t s, const void* g) {
    asm volatile("cp.async.cg.shared.global [%0], [%1], 16;" :: "r"(s), "l"(g) : "memory");
}
__device__ __forceinline__ uint32_t f2tf32(float f) {
    uint32_t u;
    asm("cvt.rna.tf32.f32 %0, %1;" : "=r"(u) : "f"(f));
    return u;
}
__device__ __forceinline__ void mma_tf32(float* c, const uint32_t* a, const uint32_t* b) {
    asm volatile(
        "mma.sync.aligned.m16n8k8.row.col.f32.tf32.tf32.f32 "
        "{%0,%1,%2,%3}, {%4,%5,%6,%7}, {%8,%9}, {%0,%1,%2,%3};"
        : "+f"(c[0]), "+f"(c[1]), "+f"(c[2]), "+f"(c[3])
        : "r"(a[0]), "r"(a[1]), "r"(a[2]), "r"(a[3]), "r"(b[0]), "r"(b[1]));
}

__device__ __forceinline__ void g_load_stage(
    uint32_t soff, const float* __restrict__ Ab, const float* __restrict__ Bb,
    int k0, int tid, int K)
{
    uint32_t dA = soff;
    uint32_t dB = soff + TBM * TSTR * 4;
    #pragma unroll
    for (int j = 0; j < 8; j++) {                 // A: 128 rows x 8 granules
        int gi  = tid + 128 * j;
        int row = gi >> 3, c = (gi & 7) * 4;
        cp16(dA + (row * TSTR + c) * 4, Ab + (size_t)row * K + k0 + c);
    }
    #pragma unroll
    for (int j = 0; j < 8; j++) {                 // B: 128 rows x 8 granules
        int gi  = tid + 128 * j;
        int row = gi >> 3, c = (gi & 7) * 4;
        cp16(dB + (row * TSTR + c) * 4, Bb + (size_t)row * K + k0 + c);
    }
    asm volatile("cp.async.commit_group;" ::: "memory");
}

// A pre-rounded: no CVT on A fragments. B cvt'd in-loop. LDS.32 throughout.
__device__ __forceinline__ void g_compute_stage(
    const float* a_s, const float* b_s, float acc[4][8][4],
    int wm, int wn, int g, int tig)
{
    #pragma unroll
    for (int ks = 0; ks < 4; ks++) {
        int kb = ks * 8;
        uint32_t af[4][4];
        #pragma unroll
        for (int mt = 0; mt < 4; mt++) {
            int r = wm + mt * 16 + g;
            af[mt][0] = __float_as_uint(a_s[ r      * TSTR + kb + tig]);
            af[mt][1] = __float_as_uint(a_s[(r + 8) * TSTR + kb + tig]);
            af[mt][2] = __float_as_uint(a_s[ r      * TSTR + kb + tig + 4]);
            af[mt][3] = __float_as_uint(a_s[(r + 8) * TSTR + kb + tig + 4]);
        }
        uint32_t bf[8][2];
        #pragma unroll
        for (int nt = 0; nt < 8; nt++) {
            int n = wn + nt * 8 + g;
            bf[nt][0] = f2tf32(b_s[n * TSTR + kb + tig]);
            bf[nt][1] = f2tf32(b_s[n * TSTR + kb + tig + 4]);
        }
        #pragma unroll
        for (int mt = 0; mt < 4; mt++)
            #pragma unroll
            for (int nt = 0; nt < 8; nt++)
                mma_tf32(acc[mt][nt], af[mt], bf[nt]);
    }
}

__global__ __launch_bounds__(128, 2) void gemm_tf32(
    const float* __restrict__ A, GemmPtrs p, int M, int N, int K)
{
    extern __shared__ float gsm[];
    const float* B = p.B[blockIdx.z];
    float*       C = p.C[blockIdx.z];

    int tid  = threadIdx.x;
    int wid  = tid >> 5;
    int lane = tid & 31;
    int bm = blockIdx.y * TBM, bn = blockIdx.x * TBN;

    int wm  = (wid & 1) * 64;
    int wn  = (wid >> 1) * 64;
    int g   = lane >> 2;
    int tig = lane & 3;

    uint32_t sbase = smem_u32(gsm);
    const float* Ab = A + (size_t)bm * K;
    const float* Bb = B + (size_t)bn * K;

    float acc[4][8][4];
    #pragma unroll
    for (int i = 0; i < 4; i++)
        #pragma unroll
        for (int j = 0; j < 8; j++)
            #pragma unroll
            for (int r = 0; r < 4; r++) acc[i][j][r] = 0.f;

    const int NIT = K / TBK;   // 128

    g_load_stage(sbase,            Ab, Bb, 0,   tid, K);
    g_load_stage(sbase + STGF * 4, Ab, Bb, TBK, tid, K);

    int cur = 0;
    for (int it = 0; it < NIT - 2; it++) {
        asm volatile("cp.async.wait_group 1;" ::: "memory");
        __syncthreads();
        int s2 = cur + 2; if (s2 >= NSTG) s2 -= NSTG;
        g_load_stage(sbase + s2 * STGF * 4, Ab, Bb, (it + 2) * TBK, tid, K);
        const float* a_s = gsm + cur * STGF;
        g_compute_stage(a_s, a_s + TBM * TSTR, acc, wm, wn, g, tig);
        if (++cur == NSTG) cur = 0;
    }
    asm volatile("cp.async.wait_group 1;" ::: "memory");
    __syncthreads();
    {
        const float* a_s = gsm + cur * STGF;
        g_compute_stage(a_s, a_s + TBM * TSTR, acc, wm, wn, g, tig);
        if (++cur == NSTG) cur = 0;
    }
    asm volatile("cp.async.wait_group 0;" ::: "memory");
    __syncthreads();
    {
        const float* a_s = gsm + cur * STGF;
        g_compute_stage(a_s, a_s + TBM * TSTR, acc, wm, wn, g, tig);
    }

    #pragma unroll
    for (int mt = 0; mt < 4; mt++) {
        #pragma unroll
        for (int nt = 0; nt < 8; nt++) {
            int row = bm + wm + mt * 16 + g;
            int col = bn + wn + nt * 8 + 2 * tig;
            float* c0 = C + (size_t)row * N + col;
            float* c1 = C + (size_t)(row + 8) * N + col;
            ((float2*)c0)[0] = make_float2(acc[mt][nt][0], acc[mt][nt][1]);
            ((float2*)c1)[0] = make_float2(acc[mt][nt][2], acc[mt][nt][3]);
        }
    }
}

// ---------------- tf32 pre-round of hidden_states (+ zero g_hsum) ---------
__global__ void rnd_kernel(const float* __restrict__ hs)
{
    int i = blockIdx.x * 256 + threadIdx.x;
    float4 v = ((const float4*)hs)[i];
    v.x = __uint_as_float(f2tf32(v.x));
    v.y = __uint_as_float(f2tf32(v.y));
    v.z = __uint_as_float(f2tf32(v.z));
    v.w = __uint_as_float(f2tf32(v.w));
    ((float4*)g_hst)[i] = v;
    if (i < HIDN) g_hsum[i] = 0.f;
}

// ---------------- RoPE in place on g_xq and g_xk --------------------------
__global__ void rope_kernel(const int* __restrict__ pos_ids)
{
    const int total = SQ * HIDN / 2;
    int i = blockIdx.x * blockDim.x + threadIdx.x;
    float* X = g_xq;
    if (i >= total) { X = g_xk; i -= total; }
    if (i >= total) return;
    int s = i / (HIDN/2);
    int r = i - s * (HIDN/2);
    int h = r >> 6, d = r & 63;
    int c = s*HIDN + h*HD + d;
    float pos = (float)pos_ids[s];
    float inv = expf((float)d * (-9.210340371976184f / 64.0f));
    float f = pos * inv;
    float cs, sn;
    sincosf(f, &sn, &cs);
    float x1 = X[c], x2 = X[c + 64];
    X[c]      = x1*cs - x2*sn;
    X[c + 64] = x2*cs + x1*sn;
}

// ---------------- fp32 top-k scoring path ---------------------------------
__global__ void hsum_kernel(const float* __restrict__ hs)
{
    int c  = blockIdx.x * 256 + threadIdx.x;
    int r0 = blockIdx.y * (SQ / 8);
    float s = 0.f;
    for (int r = r0; r < r0 + SQ / 8; r++) s += hs[(size_t)r*HIDN + c];
    atomicAdd(&g_hsum[c], s);
}

__global__ void q2sum_kernel(const float* __restrict__ Wq2)
{
    int n    = blockIdx.x * 8 + (threadIdx.x >> 5);
    int lane = threadIdx.x & 31;
    const float* row = Wq2 + (size_t)n * HIDN;
    float s = 0.f;
    for (int i = lane; i < HIDN; i += 32) s += row[i] * g_hsum[i];
    #pragma unroll
    for (int o = 16; o; o >>= 1) s += __shfl_xor_sync(0xffffffffu, s, o);
    if (lane == 0) g_q2sum[n] = s;
}

__global__ void kbscore_kernel(const float* __restrict__ kb_keys)
{
    int kb   = blockIdx.x * 8 + (threadIdx.x >> 5);
    int lane = threadIdx.x & 31;
    const float* row = kb_keys + (size_t)kb * KBSTRIDE;
    float s = 0.f;
    for (int i = lane; i < HIDN; i += 32) s += row[i] * g_q2sum[i];
    #pragma unroll
    for (int o = 16; o; o >>= 1) s += __shfl_xor_sync(0xffffffffu, s, o);
    if (lane == 0) g_kbscore[kb] = s;
}

__global__ void topk_kernel()
{
    __shared__ float sv[KBN];
    __shared__ float rv[256];
    __shared__ int   ri[256];
    int t = threadIdx.x;
    for (int i = t; i < KBN; i += 256) sv[i] = g_kbscore[i];
    __syncthreads();
    for (int it = 0; it < NTOP; it++) {
        float best = -INFINITY; int bi = 0;
        for (int i = t; i < KBN; i += 256) {
            float v = sv[i];
            if (v > best) { best = v; bi = i; }
        }
        rv[t] = best; ri[t] = bi;
        __syncthreads();
        for (int o = 128; o; o >>= 1) {
            if (t < o && rv[t+o] > rv[t]) { rv[t] = rv[t+o]; ri[t] = ri[t+o]; }
            __syncthreads();
        }
        if (t == 0) { g_topidx[it] = ri[0]; sv[ri[0]] = -INFINITY; }
        __syncthreads();
    }
}

// ---------------- mma.sync flash attention over [KB-topk ; causal self] ---
__global__ __launch_bounds__(256, 2) void attn_kernel(
    const float* __restrict__ kb_keys, const float* __restrict__ kb_values,
    const float* __restrict__ score_shift)
{
    extern __shared__ float sm[];
    float* Qs   = sm + QS_OFF;
    float* KVs  = sm + KV_OFF;
    float* Ss   = sm + SS_OFF;
    float* mrow = sm + MROW_OFF;
    float* lrow = sm + LROW_OFF;
    float* crow = sm + CROW_OFF;
    float* mnew = sm + MNEW_OFF;
    float* pmax = sm + PMAX_OFF;
    float* psum = sm + PSUM_OFF;

    int h  = blockIdx.y;
    int q0 = blockIdx.x * BMQ;
    int tid  = threadIdx.x;
    int wid  = tid >> 5;
    int lane = tid & 31;
    int g    = lane >> 2;
    int tig  = lane & 3;
    int wm   = (wid & 1) * 32;
    int wgrp = wid >> 1;
    int wn   = wgrp * 16;
    int wd   = wgrp * 32;

    float oacc[2][4][4];
    #pragma unroll
    for (int mt = 0; mt < 2; mt++)
        #pragma unroll
        for (int nt = 0; nt < 4; nt++)
            #pragma unroll
            for (int r = 0; r < 4; r++) oacc[mt][nt][r] = 0.f;

    if (tid < BMQ) { mrow[tid] = -INFINITY; lrow[tid] = 0.f; }
    float shift = score_shift[h];

    const int nkb    = (NTOP + BNK - 1) / BNK;   // 2
    const int ntiles = nkb + blockIdx.x + 1;

    for (int t = 0; t < ntiles; t++) {
        bool kbphase = (t < nkb);
        int  kb0   = (t - nkb) * BNK;
        int  jbase = t * BNK;

        if (t == 0 || t == nkb) {
            const float* src = kbphase ? g_xq2 : g_xq;
            for (int i = tid; i < BMQ*32; i += 256) {
                int row = i >> 5, c4 = i & 31;
                ((float4*)Qs)[row*33 + c4] =
                    ((const float4*)(src + (size_t)(q0+row)*HIDN + h*HD))[c4];
            }
        }
        for (int i = tid; i < BNK*32; i += 256) {
            int row = i >> 5, c4 = i & 31;
            float4 v;
            if (kbphase) {
                int j = jbase + row;
                if (j < NTOP) {
                    int kb = g_topidx[j];
                    v = ((const float4*)(kb_keys + (size_t)kb*KBSTRIDE + h*HD))[c4];
                } else v = make_float4(0.f,0.f,0.f,0.f);
            } else {
                v = ((const float4*)(g_xk + (size_t)(kb0+row)*HIDN + h*HD))[c4];
            }
            ((float4*)KVs)[row*33 + c4] = v;
        }
        __syncthreads();

        float sacc[2][2][4];
        #pragma unroll
        for (int mt = 0; mt < 2; mt++)
            #pragma unroll
            for (int nt = 0; nt < 2; nt++)
                #pragma unroll
                for (int r = 0; r < 4; r++) sacc[mt][nt][r] = 0.f;

        #pragma unroll 4
        for (int ks = 0; ks < 16; ks++) {
            int kb = ks * 8;
            uint32_t af[2][4];
            #pragma unroll
            for (int mt = 0; mt < 2; mt++) {
                int r = wm + mt * 16 + g;
                af[mt][0] = f2tf32(Qs[ r      * QSTR + kb + tig]);
                af[mt][1] = f2tf32(Qs[(r + 8) * QSTR + kb + tig]);
                af[mt][2] = f2tf32(Qs[ r      * QSTR + kb + tig + 4]);
                af[mt][3] = f2tf32(Qs[(r + 8) * QSTR + kb + tig + 4]);
            }
            uint32_t bf[2][2];
            #pragma unroll
            for (int nt = 0; nt < 2; nt++) {
                int n = wn + nt * 8 + g;
                bf[nt][0] = f2tf32(KVs[n * KSTR + kb + tig]);
                bf[nt][1] = f2tf32(KVs[n * KSTR + kb + tig + 4]);
            }
            #pragma unroll
            for (int mt = 0; mt < 2; mt++)
                #pragma unroll
                for (int nt = 0; nt < 2; nt++)
                    mma_tf32(sacc[mt][nt], af[mt], bf[nt]);
        }

        float lm0[2], lm1[2];
        #pragma unroll
        for (int mt = 0; mt < 2; mt++) { lm0[mt] = -INFINITY; lm1[mt] = -INFINITY; }
        #pragma unroll
        for (int mt = 0; mt < 2; mt++) {
            int r = wm + mt * 16 + g;
            #pragma unroll
            for (int nt = 0; nt < 2; nt++) {
                int colb = wn + nt * 8 + 2 * tig;
                #pragma unroll
                for (int c = 0; c < 2; c++) {
                    int kk = colb + c;
                    float s0 = sacc[mt][nt][c] * ATT_SCALE;
                    float s1 = sacc[mt][nt][2+c] * ATT_SCALE;
                    bool v0, v1;
                    if (kbphase) {
                        s0 += shift; s1 += shift;
                        v0 = (jbase + kk < NTOP); v1 = v0;
                    } else {
                        v0 = (kb0 + kk <= q0 + r);
                        v1 = (kb0 + kk <= q0 + r + 8);
                    }
                    s0 = v0 ? s0 : -INFINITY;
                    s1 = v1 ? s1 : -INFINITY;
                    sacc[mt][nt][c]   = s0;
                    sacc[mt][nt][2+c] = s1;
                    lm0[mt] = fmaxf(lm0[mt], s0);
                    lm1[mt] = fmaxf(lm1[mt], s1);
                }
            }
        }
        #pragma unroll
        for (int o = 1; o < 4; o <<= 1)
            #pragma unroll
            for (int mt = 0; mt < 2; mt++) {
                lm0[mt] = fmaxf(lm0[mt], __shfl_xor_sync(0xffffffffu, lm0[mt], o));
                lm1[mt] = fmaxf(lm1[mt], __shfl_xor_sync(0xffffffffu, lm1[mt], o));
            }
        if (tig == 0) {
            #pragma unroll
            for (int mt = 0; mt < 2; mt++) {
                pmax[(wm + mt*16 + g    ) * 4 + wgrp] = lm0[mt];
                pmax[(wm + mt*16 + g + 8) * 4 + wgrp] = lm1[mt];
            }
        }
        __syncthreads();

        if (tid < BMQ) {
            float mo = mrow[tid];
            float mx = fmaxf(fmaxf(pmax[tid*4], pmax[tid*4+1]),
                             fmaxf(pmax[tid*4+2], pmax[tid*4+3]));
            mx = fmaxf(mo, mx);
            mnew[tid] = mx;
            crow[tid] = (mo == -INFINITY) ? 0.f : __expf(mo - mx);
        }
        for (int i = tid; i < BNK*32; i += 256) {
            int row = i >> 5, c4 = i & 31;
            float4 v;
            if (kbphase) {
                int j = jbase + row;
                if (j < NTOP) {
                    int kb = g_topidx[j];
                    v = ((const float4*)(kb_values + (size_t)kb*KBSTRIDE + h*HD))[c4];
                } else v = make_float4(0.f,0.f,0.f,0.f);
            } else {
                v = ((const float4*)(g_xv + (size_t)(kb0+row)*HIDN + h*HD))[c4];
            }
            ((float4*)KVs)[row*34 + c4] = v;
        }
        __syncthreads();

        float ls0[2] = {0.f, 0.f}, ls1[2] = {0.f, 0.f};
        #pragma unroll
        for (int mt = 0; mt < 2; mt++) {
            int r = wm + mt * 16 + g;
            float mx0 = mnew[r], mx1 = mnew[r + 8];
            #pragma unroll
            for (int nt = 0; nt < 2; nt++) {
                int colb = wn + nt * 8 + 2 * tig;
                #pragma unroll
                for (int c = 0; c < 2; c++) {
                    float p0 = __expf(sacc[mt][nt][c]   - mx0);
                    float p1 = __expf(sacc[mt][nt][2+c] - mx1);
                    sacc[mt][nt][c]   = p0;
                    sacc[mt][nt][2+c] = p1;
                    ls0[mt] += p0; ls1[mt] += p1;
                }
                Ss[ r      * SSTR + colb    ] = sacc[mt][nt][0];
                Ss[ r      * SSTR + colb + 1] = sacc[mt][nt][1];
                Ss[(r + 8) * SSTR + colb    ] = sacc[mt][nt][2];
                Ss[(r + 8) * SSTR + colb + 1] = sacc[mt][nt][3];
            }
        }
        #pragma unroll
        for (int o = 1; o < 4; o <<= 1)
            #pragma unroll
            for (int mt = 0; mt < 2; mt++) {
                ls0[mt] += __shfl_xor_sync(0xffffffffu, ls0[mt], o);
                ls1[mt] += __shfl_xor_sync(0xffffffffu, ls1[mt], o);
            }
        if (tig == 0) {
            #pragma unroll
            for (int mt = 0; mt < 2; mt++) {
                psum[(wm + mt*16 + g    ) * 4 + wgrp] = ls0[mt];
                psum[(wm + mt*16 + g + 8) * 4 + wgrp] = ls1[mt];
            }
        }
        __syncthreads();

        if (tid < BMQ) {
            lrow[tid] = lrow[tid] * crow[tid]
                      + psum[tid*4] + psum[tid*4+1] + psum[tid*4+2] + psum[tid*4+3];
            mrow[tid] = mnew[tid];
        }
        #pragma unroll
        for (int mt = 0; mt < 2; mt++) {
            float c0 = crow[wm + mt*16 + g];
            float c1 = crow[wm + mt*16 + g + 8];
            #pragma unroll
            for (int nt = 0; nt < 4; nt++) {
                oacc[mt][nt][0] *= c0; oacc[mt][nt][1] *= c0;
                oacc[mt][nt][2] *= c1; oacc[mt][nt][3] *= c1;
            }
        }
        #pragma unroll 2
        for (int ks = 0; ks < 8; ks++) {
            int kb = ks * 8;
            uint32_t af[2][4];
            #pragma unroll
            for (int mt = 0; mt < 2; mt++) {
                int r = wm + mt * 16 + g;
                af[mt][0] = f2tf32(Ss[ r      * SSTR + kb + tig]);
                af[mt][1] = f2tf32(Ss[(r + 8) * SSTR + kb + tig]);
                af[mt][2] = f2tf32(Ss[ r      * SSTR + kb + tig + 4]);
                af[mt][3] = f2tf32(Ss[(r + 8) * SSTR + kb + tig + 4]);
            }
            uint32_t bf[4][2];
            #pragma unroll
            for (int nt = 0; nt < 4; nt++) {
                int n = wd + nt * 8 + g;
                bf[nt][0] = f2tf32(KVs[(kb + tig    ) * VSTR + n]);
                bf[nt][1] = f2tf32(KVs[(kb + tig + 4) * VSTR + n]);
            }
            #pragma unroll
            for (int mt = 0; mt < 2; mt++)
                #pragma unroll
                for (int nt = 0; nt < 4; nt++)
                    mma_tf32(oacc[mt][nt], af[mt], bf[nt]);
        }
        __syncthreads();
    }

    // output: tf32-rounded so Wo GEMM can use bits directly as A operand
    #pragma unroll
    for (int mt = 0; mt < 2; mt++) {
        int r = wm + mt * 16 + g;
        float il0 = 1.f / lrow[r];
        float il1 = 1.f / lrow[r + 8];
        float* b0 = g_attn + (size_t)(q0 + r    ) * HIDN + h*HD + wd;
        float* b1 = g_attn + (size_t)(q0 + r + 8) * HIDN + h*HD + wd;
        #pragma unroll
        for (int nt = 0; nt < 4; nt++) {
            int co = nt * 8 + 2 * tig;
            ((float2*)(b0 + co))[0] = make_float2(
                __uint_as_float(f2tf32(oacc[mt][nt][0]*il0)),
                __uint_as_float(f2tf32(oacc[mt][nt][1]*il0)));
            ((float2*)(b1 + co))[0] = make_float2(
                __uint_as_float(f2tf32(oacc[mt][nt][2]*il1)),
                __uint_as_float(f2tf32(oacc[mt][nt][3]*il1)));
        }
    }
}

// ---------------- launch ---------------------------------------------------
extern "C" void kernel_launch(void* const* d_in, const int* in_sizes, int n_in,
                              void* d_out, int out_size)
{
    const float* hs   = (const float*)d_in[0];
    const int*   pos  = (const int*)  d_in[2];
    const float* kbk  = (const float*)d_in[3];
    const float* kbv  = (const float*)d_in[4];
    const float* Wq   = (const float*)d_in[5];
    const float* Wq2  = (const float*)d_in[6];
    const float* Wk   = (const float*)d_in[7];
    const float* Wv   = (const float*)d_in[8];
    const float* Wo   = (const float*)d_in[9];
    const float* shft = (const float*)d_in[10];
    float* out = (float*)d_out;

    float *xq, *xq2, *xk, *xv, *attn, *hst;
    cudaGetSymbolAddress((void**)&xq,   g_xq);
    cudaGetSymbolAddress((void**)&xq2,  g_xq2);
    cudaGetSymbolAddress((void**)&xk,   g_xk);
    cudaGetSymbolAddress((void**)&xv,   g_xv);
    cudaGetSymbolAddress((void**)&attn, g_attn);
    cudaGetSymbolAddress((void**)&hst,  g_hst);

    cudaFuncSetAttribute(attn_kernel,
        cudaFuncAttributeMaxDynamicSharedMemorySize, ATTN_SMEM);
    cudaFuncSetAttribute(gemm_tf32,
        cudaFuncAttributeMaxDynamicSharedMemorySize, GEMM_SMEM);

    // tf32 pre-round of A operand for projections (also zeroes g_hsum)
    rnd_kernel<<<(SQ*HIDN/4)/256, 256>>>(hs);

    GemmPtrs proj;
    proj.B[0] = Wq;  proj.C[0] = xq;
    proj.B[1] = Wq2; proj.C[1] = xq2;
    proj.B[2] = Wk;  proj.C[2] = xk;
    proj.B[3] = Wv;  proj.C[3] = xv;
    dim3 gproj(HIDN/TBN, SQ/TBM, 4);   // (32, 8, 4)
    gemm_tf32<<<gproj, 128, GEMM_SMEM>>>(hst, proj, SQ, HIDN, HIDN);

    rope_kernel<<<(SQ*HIDN)/256, 256>>>(pos);

    hsum_kernel<<<dim3(HIDN/256, 8), 256>>>(hs);
    q2sum_kernel<<<HIDN/8, 256>>>(Wq2);
    kbscore_kernel<<<KBN/8, 256>>>(kbk);
    topk_kernel<<<1, 256>>>();

    attn_kernel<<<dim3(SQ/BMQ, NH), 256, ATTN_SMEM>>>(kbk, kbv, shft);

    GemmPtrs po;
    po.B[0] = Wo; po.C[0] = out;
    po.B[1] = Wo; po.C[1] = out;
    po.B[2] = Wo; po.C[2] = out;
    po.B[3] = Wo; po.C[3] = out;
    dim3 go(HIDN/TBN, SQ/TBM, 1);      // (32, 8, 1)
    gemm_tf32<<<go, 128, GEMM_SMEM>>>(attn, po, SQ, HIDN, HIDN);
}

// round 15
// speedup vs baseline: 1.1297x; 1.0377x over previous
#include <cuda_runtime.h>
#include <math.h>
#include <stdint.h>

#define SQ   1024
#define HIDN 4096
#define NH   32
#define HD   128
#define KBN  2048
#define KBSTRIDE 8192   // NUM_SLOTS * HID
#define NTOP 100
#define ATT_SCALE 0.08838834764831845f  // 1/sqrt(128)

#define BMQ 64
#define BNK 64

// ---- attention smem layout (floats), strides chosen for conflict-free frags
#define QSTR 132
#define KSTR 132
#define VSTR 136
#define SSTR 68
#define QS_OFF   0
#define KV_OFF   (64*QSTR)
#define SS_OFF   (KV_OFF + 64*VSTR)
#define MROW_OFF (SS_OFF + 64*SSTR)
#define LROW_OFF (MROW_OFF + 64)
#define CROW_OFF (LROW_OFF + 64)
#define MNEW_OFF (CROW_OFF + 64)
#define PMAX_OFF (MNEW_OFF + 64)
#define PSUM_OFF (PMAX_OFF + 256)
#define ATTN_SMEM ((PSUM_OFF + 256) * 4)      // 89088 bytes

// ---------------- device scratch (static, allocation-free) ----------------
__device__ float g_xq  [SQ*HIDN];
__device__ float g_xq2 [SQ*HIDN];
__device__ float g_xk  [SQ*HIDN];
__device__ float g_xv  [SQ*HIDN];
__device__ float g_attn[SQ*HIDN];   // tf32-rounded by attn epilogue
__device__ float g_hst [SQ*HIDN];   // tf32-rounded copy of hidden_states
__device__ float g_hsum [HIDN];
__device__ float g_q2sum[HIDN];
__device__ float g_kbscore[KBN];
__device__ int   g_topidx[NTOP];

// ======================= tf32 mma.sync GEMM ================================
// CTA tile 128x128, 4 warps (2m x 2n), warp tile 64x64. TBK=32, 3-stage
// cp.async ring, branch-free mainloop, 2 CTAs/SM. A pre-rounded to tf32.
// Fragment loads LDS.32 with conflict-free banks (4g+tig, stride 36).
// Optional fused RoPE epilogue (rope_mask bit per blockIdx.z).
#define TBM 128
#define TBN 128
#define TBK 32
#define TSTR 36                            // 32 data + 4 pad
#define NSTG 3
#define STGF ((TBM + TBN) * TSTR)          // 9216 floats / stage
#define GEMM_SMEM (NSTG * STGF * 4)        // 110592 bytes

struct GemmPtrs {
    const float* B[4];
    float*       C[4];
};

__device__ __forceinline__ uint32_t smem_u32(const void* p) {
    uint32_t a;
    asm("{ .reg .u64 t; cvta.to.shared.u64 t, %1; cvt.u32.u64 %0, t; }"
        : "=r"(a) : "l"(p));
    return a;
}
__device__ __forceinline__ void cp16(uint32_t s, const void* g) {
    asm volatile("cp.async.cg.shared.global [%0], [%1], 16;" :: "r"(s), "l"(g) : "memory");
}
__device__ __forceinline__ uint32_t f2tf32(float f) {
    uint32_t u;
    asm("cvt.rna.tf32.f32 %0, %1;" : "=r"(u) : "f"(f));
    return u;
}
__device__ __forceinline__ void mma_tf32(float* c, const uint32_t* a, const uint32_t* b) {
    asm volatile(
        "mma.sync.aligned.m16n8k8.row.col.f32.tf32.tf32.f32 "
        "{%0,%1,%2,%3}, {%4,%5,%6,%7}, {%8,%9}, {%0,%1,%2,%3};"
        : "+f"(c[0]), "+f"(c[1]), "+f"(c[2]), "+f"(c[3])
        : "r"(a[0]), "r"(a[1]), "r"(a[2]), "r"(a[3]), "r"(b[0]), "r"(b[1]));
}

__device__ __forceinline__ void g_load_stage(
    uint32_t soff, const float* __restrict__ Ab, const float* __restrict__ Bb,
    int k0, int tid, int K)
{
    uint32_t dA = soff;
    uint32_t dB = soff + TBM * TSTR * 4;
    #pragma unroll
    for (int j = 0; j < 8; j++) {
        int gi  = tid + 128 * j;
        int row = gi >> 3, c = (gi & 7) * 4;
        cp16(dA + (row * TSTR + c) * 4, Ab + (size_t)row * K + k0 + c);
    }
    #pragma unroll
    for (int j = 0; j < 8; j++) {
        int gi  = tid + 128 * j;
        int row = gi >> 3, c = (gi & 7) * 4;
        cp16(dB + (row * TSTR + c) * 4, Bb + (size_t)row * K + k0 + c);
    }
    asm volatile("cp.async.commit_group;" ::: "memory");
}

__device__ __forceinline__ void g_compute_stage(
    const float* a_s, const float* b_s, float acc[4][8][4],
    int wm, int wn, int g, int tig)
{
    #pragma unroll
    for (int ks = 0; ks < 4; ks++) {
        int kb = ks * 8;
        uint32_t af[4][4];
        #pragma unroll
        for (int mt = 0; mt < 4; mt++) {
            int r = wm + mt * 16 + g;
            af[mt][0] = __float_as_uint(a_s[ r      * TSTR + kb + tig]);
            af[mt][1] = __float_as_uint(a_s[(r + 8) * TSTR + kb + tig]);
            af[mt][2] = __float_as_uint(a_s[ r      * TSTR + kb + tig + 4]);
            af[mt][3] = __float_as_uint(a_s[(r + 8) * TSTR + kb + tig + 4]);
        }
        uint32_t bf[8][2];
        #pragma unroll
        for (int nt = 0; nt < 8; nt++) {
            int n = wn + nt * 8 + g;
            bf[nt][0] = f2tf32(b_s[n * TSTR + kb + tig]);
            bf[nt][1] = f2tf32(b_s[n * TSTR + kb + tig + 4]);
        }
        #pragma unroll
        for (int mt = 0; mt < 4; mt++)
            #pragma unroll
            for (int nt = 0; nt < 8; nt++)
                mma_tf32(acc[mt][nt], af[mt], bf[nt]);
    }
}

__global__ __launch_bounds__(128, 2) void gemm_tf32(
    const float* __restrict__ A, GemmPtrs p, const int* __restrict__ pos_ids,
    int rope_mask, int M, int N, int K)
{
    extern __shared__ float gsm[];
    const float* B = p.B[blockIdx.z];
    float*       C = p.C[blockIdx.z];

    int tid  = threadIdx.x;
    int wid  = tid >> 5;
    int lane = tid & 31;
    int bm = blockIdx.y * TBM, bn = blockIdx.x * TBN;

    int wm  = (wid & 1) * 64;
    int wn  = (wid >> 1) * 64;
    int g   = lane >> 2;
    int tig = lane & 3;

    uint32_t sbase = smem_u32(gsm);
    const float* Ab = A + (size_t)bm * K;
    const float* Bb = B + (size_t)bn * K;

    float acc[4][8][4];
    #pragma unroll
    for (int i = 0; i < 4; i++)
        #pragma unroll
        for (int j = 0; j < 8; j++)
            #pragma unroll
            for (int r = 0; r < 4; r++) acc[i][j][r] = 0.f;

    const int NIT = K / TBK;   // 128

    g_load_stage(sbase,            Ab, Bb, 0,   tid, K);
    g_load_stage(sbase + STGF * 4, Ab, Bb, TBK, tid, K);

    int cur = 0;
    for (int it = 0; it < NIT - 2; it++) {
        asm volatile("cp.async.wait_group 1;" ::: "memory");
        __syncthreads();
        int s2 = cur + 2; if (s2 >= NSTG) s2 -= NSTG;
        g_load_stage(sbase + s2 * STGF * 4, Ab, Bb, (it + 2) * TBK, tid, K);
        const float* a_s = gsm + cur * STGF;
        g_compute_stage(a_s, a_s + TBM * TSTR, acc, wm, wn, g, tig);
        if (++cur == NSTG) cur = 0;
    }
    asm volatile("cp.async.wait_group 1;" ::: "memory");
    __syncthreads();
    {
        const float* a_s = gsm + cur * STGF;
        g_compute_stage(a_s, a_s + TBM * TSTR, acc, wm, wn, g, tig);
        if (++cur == NSTG) cur = 0;
    }
    asm volatile("cp.async.wait_group 0;" ::: "memory");
    __syncthreads();
    {
        const float* a_s = gsm + cur * STGF;
        g_compute_stage(a_s, a_s + TBM * TSTR, acc, wm, wn, g, tig);
    }

    if ((rope_mask >> blockIdx.z) & 1) {
        // fused RoPE epilogue: stage tile to smem, pair (d, d+64) within head
        __syncthreads();
        float* st = gsm;   // 128 x 132 floats
        #pragma unroll
        for (int mt = 0; mt < 4; mt++)
            #pragma unroll
            for (int nt = 0; nt < 8; nt++) {
                int r = wm + mt * 16 + g;
                int c = wn + nt * 8 + 2 * tig;
                st[ r      * 132 + c    ] = acc[mt][nt][0];
                st[ r      * 132 + c + 1] = acc[mt][nt][1];
                st[(r + 8) * 132 + c    ] = acc[mt][nt][2];
                st[(r + 8) * 132 + c + 1] = acc[mt][nt][3];
            }
        __syncthreads();
        for (int idx = tid; idx < TBM * 64; idx += 128) {
            int r  = idx >> 6;
            int cl = idx & 63;
            float a = st[r * 132 + cl];
            float b = st[r * 132 + cl + 64];
            float pos = (float)pos_ids[bm + r];
            float inv = expf((float)cl * (-9.210340371976184f / 64.0f));
            float f = pos * inv;
            float cs, sn;
            sincosf(f, &sn, &cs);
            C[(size_t)(bm + r) * N + bn + cl     ] = a * cs - b * sn;
            C[(size_t)(bm + r) * N + bn + cl + 64] = b * cs + a * sn;
        }
    } else {
        #pragma unroll
        for (int mt = 0; mt < 4; mt++) {
            #pragma unroll
            for (int nt = 0; nt < 8; nt++) {
                int row = bm + wm + mt * 16 + g;
                int col = bn + wn + nt * 8 + 2 * tig;
                float* c0 = C + (size_t)row * N + col;
                float* c1 = C + (size_t)(row + 8) * N + col;
                ((float2*)c0)[0] = make_float2(acc[mt][nt][0], acc[mt][nt][1]);
                ((float2*)c1)[0] = make_float2(acc[mt][nt][2], acc[mt][nt][3]);
            }
        }
    }
}

// ---------------- tf32 pre-round of hidden_states (+ zero g_hsum) ---------
__global__ void rnd_kernel(const float* __restrict__ hs)
{
    int i = blockIdx.x * 256 + threadIdx.x;
    float4 v = ((const float4*)hs)[i];
    v.x = __uint_as_float(f2tf32(v.x));
    v.y = __uint_as_float(f2tf32(v.y));
    v.z = __uint_as_float(f2tf32(v.z));
    v.w = __uint_as_float(f2tf32(v.w));
    ((float4*)g_hst)[i] = v;
    if (i < HIDN) g_hsum[i] = 0.f;
}

// ---------------- fp32 top-k scoring path ---------------------------------
__global__ void hsum_kernel(const float* __restrict__ hs)
{
    int c  = blockIdx.x * 256 + threadIdx.x;
    int r0 = blockIdx.y * (SQ / 8);
    float s = 0.f;
    for (int r = r0; r < r0 + SQ / 8; r++) s += hs[(size_t)r*HIDN + c];
    atomicAdd(&g_hsum[c], s);
}

__global__ void q2sum_kernel(const float* __restrict__ Wq2)
{
    int n    = blockIdx.x * 8 + (threadIdx.x >> 5);
    int lane = threadIdx.x & 31;
    const float* row = Wq2 + (size_t)n * HIDN;
    float s = 0.f;
    for (int i = lane; i < HIDN; i += 32) s += row[i] * g_hsum[i];
    #pragma unroll
    for (int o = 16; o; o >>= 1) s += __shfl_xor_sync(0xffffffffu, s, o);
    if (lane == 0) g_q2sum[n] = s;
}

__global__ void kbscore_kernel(const float* __restrict__ kb_keys)
{
    int kb   = blockIdx.x * 8 + (threadIdx.x >> 5);
    int lane = threadIdx.x & 31;
    const float* row = kb_keys + (size_t)kb * KBSTRIDE;
    float s = 0.f;
    for (int i = lane; i < HIDN; i += 32) s += row[i] * g_q2sum[i];
    #pragma unroll
    for (int o = 16; o; o >>= 1) s += __shfl_xor_sync(0xffffffffu, s, o);
    if (lane == 0) g_kbscore[kb] = s;
}

// top-100 by iterative argmax: warp-shfl reduce, 2 syncthreads per iter
__global__ void topk_kernel()
{
    __shared__ float sv[KBN];
    __shared__ float wbest[8];
    __shared__ int   wbi[8];
    __shared__ int   sel;
    int tid  = threadIdx.x;
    int wid  = tid >> 5;
    int lane = tid & 31;
    for (int i = tid; i < KBN; i += 256) sv[i] = g_kbscore[i];
    __syncthreads();
    for (int it = 0; it < NTOP; it++) {
        float best = -INFINITY; int bi = 0;
        #pragma unroll
        for (int j = 0; j < KBN / 256; j++) {
            int i = j * 256 + tid;
            float v = sv[i];
            if (v > best) { best = v; bi = i; }
        }
        #pragma unroll
        for (int o = 16; o; o >>= 1) {
            float ov = __shfl_xor_sync(0xffffffffu, best, o);
            int   oi = __shfl_xor_sync(0xffffffffu, bi,   o);
            if (ov > best) { best = ov; bi = oi; }
        }
        if (lane == 0) { wbest[wid] = best; wbi[wid] = bi; }
        __syncthreads();
        if (tid == 0) {
            float b = wbest[0]; int x = wbi[0];
            #pragma unroll
            for (int w = 1; w < 8; w++)
                if (wbest[w] > b) { b = wbest[w]; x = wbi[w]; }
            g_topidx[it] = x;
            sel = x;
            sv[x] = -INFINITY;
        }
        __syncthreads();
        (void)sel;
    }
}

// ---------------- mma.sync flash attention over [KB-topk ; causal self] ---
__global__ __launch_bounds__(256, 2) void attn_kernel(
    const float* __restrict__ kb_keys, const float* __restrict__ kb_values,
    const float* __restrict__ score_shift)
{
    extern __shared__ float sm[];
    float* Qs   = sm + QS_OFF;
    float* KVs  = sm + KV_OFF;
    float* Ss   = sm + SS_OFF;
    float* mrow = sm + MROW_OFF;
    float* lrow = sm + LROW_OFF;
    float* crow = sm + CROW_OFF;
    float* mnew = sm + MNEW_OFF;
    float* pmax = sm + PMAX_OFF;
    float* psum = sm + PSUM_OFF;

    int h  = blockIdx.y;
    int q0 = blockIdx.x * BMQ;
    int tid  = threadIdx.x;
    int wid  = tid >> 5;
    int lane = tid & 31;
    int g    = lane >> 2;
    int tig  = lane & 3;
    int wm   = (wid & 1) * 32;
    int wgrp = wid >> 1;
    int wn   = wgrp * 16;
    int wd   = wgrp * 32;

    float oacc[2][4][4];
    #pragma unroll
    for (int mt = 0; mt < 2; mt++)
        #pragma unroll
        for (int nt = 0; nt < 4; nt++)
            #pragma unroll
            for (int r = 0; r < 4; r++) oacc[mt][nt][r] = 0.f;

    if (tid < BMQ) { mrow[tid] = -INFINITY; lrow[tid] = 0.f; }
    float shift = score_shift[h];

    const int nkb    = (NTOP + BNK - 1) / BNK;   // 2
    const int ntiles = nkb + blockIdx.x + 1;

    for (int t = 0; t < ntiles; t++) {
        bool kbphase = (t < nkb);
        int  kb0   = (t - nkb) * BNK;
        int  jbase = t * BNK;

        if (t == 0 || t == nkb) {
            const float* src = kbphase ? g_xq2 : g_xq;
            for (int i = tid; i < BMQ*32; i += 256) {
                int row = i >> 5, c4 = i & 31;
                ((float4*)Qs)[row*33 + c4] =
                    ((const float4*)(src + (size_t)(q0+row)*HIDN + h*HD))[c4];
            }
        }
        for (int i = tid; i < BNK*32; i += 256) {
            int row = i >> 5, c4 = i & 31;
            float4 v;
            if (kbphase) {
                int j = jbase + row;
                if (j < NTOP) {
                    int kb = g_topidx[j];
                    v = ((const float4*)(kb_keys + (size_t)kb*KBSTRIDE + h*HD))[c4];
                } else v = make_float4(0.f,0.f,0.f,0.f);
            } else {
                v = ((const float4*)(g_xk + (size_t)(kb0+row)*HIDN + h*HD))[c4];
            }
            ((float4*)KVs)[row*33 + c4] = v;
        }
        __syncthreads();

        float sacc[2][2][4];
        #pragma unroll
        for (int mt = 0; mt < 2; mt++)
            #pragma unroll
            for (int nt = 0; nt < 2; nt++)
                #pragma unroll
                for (int r = 0; r < 4; r++) sacc[mt][nt][r] = 0.f;

        #pragma unroll 4
        for (int ks = 0; ks < 16; ks++) {
            int kb = ks * 8;
            uint32_t af[2][4];
            #pragma unroll
            for (int mt = 0; mt < 2; mt++) {
                int r = wm + mt * 16 + g;
                af[mt][0] = f2tf32(Qs[ r      * QSTR + kb + tig]);
                af[mt][1] = f2tf32(Qs[(r + 8) * QSTR + kb + tig]);
                af[mt][2] = f2tf32(Qs[ r      * QSTR + kb + tig + 4]);
                af[mt][3] = f2tf32(Qs[(r + 8) * QSTR + kb + tig + 4]);
            }
            uint32_t bf[2][2];
            #pragma unroll
            for (int nt = 0; nt < 2; nt++) {
                int n = wn + nt * 8 + g;
                bf[nt][0] = f2tf32(KVs[n * KSTR + kb + tig]);
                bf[nt][1] = f2tf32(KVs[n * KSTR + kb + tig + 4]);
            }
            #pragma unroll
            for (int mt = 0; mt < 2; mt++)
                #pragma unroll
                for (int nt = 0; nt < 2; nt++)
                    mma_tf32(sacc[mt][nt], af[mt], bf[nt]);
        }

        float lm0[2], lm1[2];
        #pragma unroll
        for (int mt = 0; mt < 2; mt++) { lm0[mt] = -INFINITY; lm1[mt] = -INFINITY; }
        #pragma unroll
        for (int mt = 0; mt < 2; mt++) {
            int r = wm + mt * 16 + g;
            #pragma unroll
            for (int nt = 0; nt < 2; nt++) {
                int colb = wn + nt * 8 + 2 * tig;
                #pragma unroll
                for (int c = 0; c < 2; c++) {
                    int kk = colb + c;
                    float s0 = sacc[mt][nt][c] * ATT_SCALE;
                    float s1 = sacc[mt][nt][2+c] * ATT_SCALE;
                    bool v0, v1;
                    if (kbphase) {
                        s0 += shift; s1 += shift;
                        v0 = (jbase + kk < NTOP); v1 = v0;
                    } else {
                        v0 = (kb0 + kk <= q0 + r);
                        v1 = (kb0 + kk <= q0 + r + 8);
                    }
                    s0 = v0 ? s0 : -INFINITY;
                    s1 = v1 ? s1 : -INFINITY;
                    sacc[mt][nt][c]   = s0;
                    sacc[mt][nt][2+c] = s1;
                    lm0[mt] = fmaxf(lm0[mt], s0);
                    lm1[mt] = fmaxf(lm1[mt], s1);
                }
            }
        }
        #pragma unroll
        for (int o = 1; o < 4; o <<= 1)
            #pragma unroll
            for (int mt = 0; mt < 2; mt++) {
                lm0[mt] = fmaxf(lm0[mt], __shfl_xor_sync(0xffffffffu, lm0[mt], o));
                lm1[mt] = fmaxf(lm1[mt], __shfl_xor_sync(0xffffffffu, lm1[mt], o));
            }
        if (tig == 0) {
            #pragma unroll
            for (int mt = 0; mt < 2; mt++) {
                pmax[(wm + mt*16 + g    ) * 4 + wgrp] = lm0[mt];
                pmax[(wm + mt*16 + g + 8) * 4 + wgrp] = lm1[mt];
            }
        }
        __syncthreads();

        if (tid < BMQ) {
            float mo = mrow[tid];
            float mx = fmaxf(fmaxf(pmax[tid*4], pmax[tid*4+1]),
                             fmaxf(pmax[tid*4+2], pmax[tid*4+3]));
            mx = fmaxf(mo, mx);
            mnew[tid] = mx;
            crow[tid] = (mo == -INFINITY) ? 0.f : __expf(mo - mx);
        }
        for (int i = tid; i < BNK*32; i += 256) {
            int row = i >> 5, c4 = i & 31;
            float4 v;
            if (kbphase) {
                int j = jbase + row;
                if (j < NTOP) {
                    int kb = g_topidx[j];
                    v = ((const float4*)(kb_values + (size_t)kb*KBSTRIDE + h*HD))[c4];
                } else v = make_float4(0.f,0.f,0.f,0.f);
            } else {
                v = ((const float4*)(g_xv + (size_t)(kb0+row)*HIDN + h*HD))[c4];
            }
            ((float4*)KVs)[row*34 + c4] = v;
        }
        __syncthreads();

        float ls0[2] = {0.f, 0.f}, ls1[2] = {0.f, 0.f};
        #pragma unroll
        for (int mt = 0; mt < 2; mt++) {
            int r = wm + mt * 16 + g;
            float mx0 = mnew[r], mx1 = mnew[r + 8];
            #pragma unroll
            for (int nt = 0; nt < 2; nt++) {
                int colb = wn + nt * 8 + 2 * tig;
                #pragma unroll
                for (int c = 0; c < 2; c++) {
                    float p0 = __expf(sacc[mt][nt][c]   - mx0);
                    float p1 = __expf(sacc[mt][nt][2+c] - mx1);
                    sacc[mt][nt][c]   = p0;
                    sacc[mt][nt][2+c] = p1;
                    ls0[mt] += p0; ls1[mt] += p1;
                }
                Ss[ r      * SSTR + colb    ] = sacc[mt][nt][0];
                Ss[ r      * SSTR + colb + 1] = sacc[mt][nt][1];
                Ss[(r + 8) * SSTR + colb    ] = sacc[mt][nt][2];
                Ss[(r + 8) * SSTR + colb + 1] = sacc[mt][nt][3];
            }
        }
        #pragma unroll
        for (int o = 1; o < 4; o <<= 1)
            #pragma unroll
            for (int mt = 0; mt < 2; mt++) {
                ls0[mt] += __shfl_xor_sync(0xffffffffu, ls0[mt], o);
                ls1[mt] += __shfl_xor_sync(0xffffffffu, ls1[mt], o);
            }
        if (tig == 0) {
            #pragma unroll
            for (int mt = 0; mt < 2; mt++) {
                psum[(wm + mt*16 + g    ) * 4 + wgrp] = ls0[mt];
                psum[(wm + mt*16 + g + 8) * 4 + wgrp] = ls1[mt];
            }
        }
        __syncthreads();

        if (tid < BMQ) {
            lrow[tid] = lrow[tid] * crow[tid]
                      + psum[tid*4] + psum[tid*4+1] + psum[tid*4+2] + psum[tid*4+3];
            mrow[tid] = mnew[tid];
        }
        #pragma unroll
        for (int mt = 0; mt < 2; mt++) {
            float c0 = crow[wm + mt*16 + g];
            float c1 = crow[wm + mt*16 + g + 8];
            #pragma unroll
            for (int nt = 0; nt < 4; nt++) {
                oacc[mt][nt][0] *= c0; oacc[mt][nt][1] *= c0;
                oacc[mt][nt][2] *= c1; oacc[mt][nt][3] *= c1;
            }
        }
        #pragma unroll 2
        for (int ks = 0; ks < 8; ks++) {
            int kb = ks * 8;
            uint32_t af[2][4];
            #pragma unroll
            for (int mt = 0; mt < 2; mt++) {
                int r = wm + mt * 16 + g;
                af[mt][0] = f2tf32(Ss[ r      * SSTR + kb + tig]);
                af[mt][1] = f2tf32(Ss[(r + 8) * SSTR + kb + tig]);
                af[mt][2] = f2tf32(Ss[ r      * SSTR + kb + tig + 4]);
                af[mt][3] = f2tf32(Ss[(r + 8) * SSTR + kb + tig + 4]);
            }
            uint32_t bf[4][2];
            #pragma unroll
            for (int nt = 0; nt < 4; nt++) {
                int n = wd + nt * 8 + g;
                bf[nt][0] = f2tf32(KVs[(kb + tig    ) * VSTR + n]);
                bf[nt][1] = f2tf32(KVs[(kb + tig + 4) * VSTR + n]);
            }
            #pragma unroll
            for (int mt = 0; mt < 2; mt++)
                #pragma unroll
                for (int nt = 0; nt < 4; nt++)
                    mma_tf32(oacc[mt][nt], af[mt], bf[nt]);
        }
        __syncthreads();
    }

    // output: tf32-rounded so Wo GEMM can use bits directly as A operand
    #pragma unroll
    for (int mt = 0; mt < 2; mt++) {
        int r = wm + mt * 16 + g;
        float il0 = 1.f / lrow[r];
        float il1 = 1.f / lrow[r + 8];
        float* b0 = g_attn + (size_t)(q0 + r    ) * HIDN + h*HD + wd;
        float* b1 = g_attn + (size_t)(q0 + r + 8) * HIDN + h*HD + wd;
        #pragma unroll
        for (int nt = 0; nt < 4; nt++) {
            int co = nt * 8 + 2 * tig;
            ((float2*)(b0 + co))[0] = make_float2(
                __uint_as_float(f2tf32(oacc[mt][nt][0]*il0)),
                __uint_as_float(f2tf32(oacc[mt][nt][1]*il0)));
            ((float2*)(b1 + co))[0] = make_float2(
                __uint_as_float(f2tf32(oacc[mt][nt][2]*il1)),
                __uint_as_float(f2tf32(oacc[mt][nt][3]*il1)));
        }
    }
}

// ---------------- launch ---------------------------------------------------
extern "C" void kernel_launch(void* const* d_in, const int* in_sizes, int n_in,
                              void* d_out, int out_size)
{
    const float* hs   = (const float*)d_in[0];
    const int*   pos  = (const int*)  d_in[2];
    const float* kbk  = (const float*)d_in[3];
    const float* kbv  = (const float*)d_in[4];
    const float* Wq   = (const float*)d_in[5];
    const float* Wq2  = (const float*)d_in[6];
    const float* Wk   = (const float*)d_in[7];
    const float* Wv   = (const float*)d_in[8];
    const float* Wo   = (const float*)d_in[9];
    const float* shft = (const float*)d_in[10];
    float* out = (float*)d_out;

    float *xq, *xq2, *xk, *xv, *attn, *hst;
    cudaGetSymbolAddress((void**)&xq,   g_xq);
    cudaGetSymbolAddress((void**)&xq2,  g_xq2);
    cudaGetSymbolAddress((void**)&xk,   g_xk);
    cudaGetSymbolAddress((void**)&xv,   g_xv);
    cudaGetSymbolAddress((void**)&attn, g_attn);
    cudaGetSymbolAddress((void**)&hst,  g_hst);

    cudaFuncSetAttribute(attn_kernel,
        cudaFuncAttributeMaxDynamicSharedMemorySize, ATTN_SMEM);
    cudaFuncSetAttribute(gemm_tf32,
        cudaFuncAttributeMaxDynamicSharedMemorySize, GEMM_SMEM);

    // tf32 pre-round of A operand for projections (also zeroes g_hsum)
    rnd_kernel<<<(SQ*HIDN/4)/256, 256>>>(hs);

    // fused Q/Q2/K/V projections; RoPE fused into epilogue for z=0 (q), z=2 (k)
    GemmPtrs proj;
    proj.B[0] = Wq;  proj.C[0] = xq;
    proj.B[1] = Wq2; proj.C[1] = xq2;
    proj.B[2] = Wk;  proj.C[2] = xk;
    proj.B[3] = Wv;  proj.C[3] = xv;
    dim3 gproj(HIDN/TBN, SQ/TBM, 4);   // (32, 8, 4)
    gemm_tf32<<<gproj, 128, GEMM_SMEM>>>(hst, proj, pos, 0x5, SQ, HIDN, HIDN);

    hsum_kernel<<<dim3(HIDN/256, 8), 256>>>(hs);
    q2sum_kernel<<<HIDN/8, 256>>>(Wq2);
    kbscore_kernel<<<KBN/8, 256>>>(kbk);
    topk_kernel<<<1, 256>>>();

    attn_kernel<<<dim3(SQ/BMQ, NH), 256, ATTN_SMEM>>>(kbk, kbv, shft);

    GemmPtrs po;
    po.B[0] = Wo; po.C[0] = out;
    po.B[1] = Wo; po.C[1] = out;
    po.B[2] = Wo; po.C[2] = out;
    po.B[3] = Wo; po.C[3] = out;
    dim3 go(HIDN/TBN, SQ/TBM, 1);      // (32, 8, 1)
    gemm_tf32<<<go, 128, GEMM_SMEM>>>(attn, po, pos, 0x0, SQ, HIDN, HIDN);
}